// round 5
// baseline (speedup 1.0000x reference)
#include <cuda_runtime.h>
#include <cuda_bf16.h>
#include <cstdint>

#define T_LEN    8192
#define L_WIN    64
#define TP_LEN   (T_LEN - L_WIN + 1)   // 8129
#define P_NUM    64
#define BS       32
#define TILE_M   128
#define PAD_LEFT 32
#define EPS      1e-6f

// smem layout (dynamic): A [128][136] bf16, B [64][136] bf16
#define SA       136                    // k-stride (bf16) with +8 pad
#define A_BYTES  (TILE_M * SA * 2)      // 34816
#define B_BYTES  (P_NUM  * SA * 2)      // 17408
#define DYN_SMEM (A_BYTES + B_BYTES)    // 52224
#define STG_W    68                     // fp32 staging stride (reuses A region: 128*68*4 = 34816)

union Pack8 { __nv_bfloat16 h[8]; uint4 u; };

__device__ __forceinline__ void mma_16816_bf16(
    float& c0, float& c1, float& c2, float& c3,
    uint32_t a0, uint32_t a1, uint32_t a2, uint32_t a3,
    uint32_t b0, uint32_t b1)
{
    asm volatile(
        "mma.sync.aligned.m16n8k16.row.col.f32.bf16.bf16.f32 "
        "{%0,%1,%2,%3}, {%4,%5,%6,%7}, {%8,%9}, {%0,%1,%2,%3};"
        : "+f"(c0), "+f"(c1), "+f"(c2), "+f"(c3)
        : "r"(a0), "r"(a1), "r"(a2), "r"(a3), "r"(b0), "r"(b1));
}

// ---------------------------------------------------------------------------
// Fused kernel: 128 windows x 64 shapelets per CTA via mma.sync bf16 (3-term
// hi/lo split: dot = hix*his + hix*los + lox*his). Epilogue folds window
// z-norm: act = exp(2*inv*dot - w2 - s2[p]).
// ---------------------------------------------------------------------------
__global__ void __launch_bounds__(128)
shapelet_hmma_kernel(const float* __restrict__ x,
                     const float* __restrict__ sh,
                     float* __restrict__ out)
{
    extern __shared__ char dyn[];
    __nv_bfloat16* As = reinterpret_cast<__nv_bfloat16*>(dyn);
    __nv_bfloat16* Bs = reinterpret_cast<__nv_bfloat16*>(dyn + A_BYTES);

    __shared__ float xs[TILE_M + L_WIN];     // 192 raw x values
    __shared__ float invs[TILE_M];
    __shared__ float w2s[TILE_M];
    __shared__ float s2s[P_NUM];

    const int tid = threadIdx.x;
    const int b   = blockIdx.y;
    const int t0  = blockIdx.x * TILE_M;

    // ---- load raw x segment (zero past T) ----
    {
        const float* xb = x + (size_t)b * T_LEN;
        int i0 = t0 + tid;
        xs[tid] = (i0 < T_LEN) ? xb[i0] : 0.f;
        if (tid < L_WIN) {
            int i1 = t0 + TILE_M + tid;
            xs[TILE_M + tid] = (i1 < T_LEN) ? xb[i1] : 0.f;
        }
    }
    __syncthreads();

    // ---- per-window stats (thread tid <-> local window tid) ----
    {
        float s1 = 0.f, sq = 0.f;
        #pragma unroll
        for (int l = 0; l < L_WIN; l++) {
            float v = xs[tid + l];
            s1 += v; sq = fmaf(v, v, sq);
        }
        float mu  = s1 * (1.f / L_WIN);
        float var = fmaxf(sq * (1.f / L_WIN) - mu * mu, 0.f);
        float sd  = sqrtf(var);
        float inv = 1.f / fmaxf(sd, EPS);
        invs[tid] = inv;
        w2s[tid]  = var * inv * inv * (float)L_WIN;
    }

    // ---- build A tile: row = window tid; k<64: hix[row+k], k>=64: lox[row+k-64] ----
    {
        __nv_bfloat16* Arow = As + tid * SA;
        #pragma unroll
        for (int g = 0; g < 8; g++) {
            Pack8 hi, lo;
            #pragma unroll
            for (int j = 0; j < 8; j++) {
                float v = xs[tid + g * 8 + j];
                __nv_bfloat16 h = __float2bfloat16(v);
                hi.h[j] = h;
                lo.h[j] = __float2bfloat16(v - __bfloat162float(h));
            }
            *reinterpret_cast<uint4*>(Arow + g * 8)      = hi.u;
            *reinterpret_cast<uint4*>(Arow + 64 + g * 8) = lo.u;
        }
    }

    // ---- shapelet z-norm + B tile (threads 0..63; row = shapelet p) ----
    if (tid < P_NUM) {
        const int p = tid;
        const float* row = sh + (size_t)p * L_WIN;
        float rv[L_WIN];
        float s1 = 0.f, sq = 0.f;
        #pragma unroll
        for (int l = 0; l < L_WIN; l++) {
            float v = row[l];
            rv[l] = v; s1 += v; sq = fmaf(v, v, sq);
        }
        float mu  = s1 * (1.f / L_WIN);
        float var = fmaxf(sq * (1.f / L_WIN) - mu * mu, 0.f);
        float sd  = sqrtf(var);
        float inv = 1.f / fmaxf(sd, EPS);
        float s2  = 0.f;
        __nv_bfloat16* Brow = Bs + p * SA;
        #pragma unroll
        for (int g = 0; g < 8; g++) {
            Pack8 hi, lo;
            #pragma unroll
            for (int j = 0; j < 8; j++) {
                float sn = (rv[g * 8 + j] - mu) * inv;
                s2 = fmaf(sn, sn, s2);
                __nv_bfloat16 h = __float2bfloat16(sn);
                hi.h[j] = h;
                lo.h[j] = __float2bfloat16(sn - __bfloat162float(h));
            }
            *reinterpret_cast<uint4*>(Brow + g * 8)      = hi.u;
            *reinterpret_cast<uint4*>(Brow + 64 + g * 8) = lo.u;
        }
        s2s[p] = s2;
    }
    __syncthreads();

    // ---- MMA mainloop ----
    // warp w owns rows [32w, 32w+32); mtile m: rows 32w+16m..+15
    const int lane = tid & 31;
    const int wrp  = tid >> 5;
    const int g    = lane >> 2;        // group id 0..7
    const int tq   = lane & 3;

    float c[2][8][4];
    #pragma unroll
    for (int m = 0; m < 2; m++)
        #pragma unroll
        for (int nt = 0; nt < 8; nt++)
            #pragma unroll
            for (int r = 0; r < 4; r++) c[m][nt][r] = 0.f;

    // logical K-steps s=0..11:
    //   s 0..3 : A phys ks = s     (hix), B phys ks = s      (his)
    //   s 4..7 : A phys ks = s - 4 (hix), B phys ks = s      (los)
    //   s 8..11: A phys ks = s - 4 (lox), B phys ks = s - 8  (his)
    #pragma unroll
    for (int s = 0; s < 12; s++) {
        const int ka = (s < 4) ? s : (s - 4);
        const int kb = (s < 8) ? s : (s - 8);

        uint32_t a[2][4];
        #pragma unroll
        for (int m = 0; m < 2; m++) {
            const __nv_bfloat16* ar = As + (wrp * 32 + m * 16 + g) * SA + ka * 16 + tq * 2;
            a[m][0] = *reinterpret_cast<const uint32_t*>(ar);
            a[m][1] = *reinterpret_cast<const uint32_t*>(ar + 8 * SA);
            a[m][2] = *reinterpret_cast<const uint32_t*>(ar + 8);
            a[m][3] = *reinterpret_cast<const uint32_t*>(ar + 8 * SA + 8);
        }
        #pragma unroll
        for (int nt = 0; nt < 8; nt++) {
            const __nv_bfloat16* br = Bs + (nt * 8 + g) * SA + kb * 16 + tq * 2;
            uint32_t b0 = *reinterpret_cast<const uint32_t*>(br);
            uint32_t b1 = *reinterpret_cast<const uint32_t*>(br + 8);
            mma_16816_bf16(c[0][nt][0], c[0][nt][1], c[0][nt][2], c[0][nt][3],
                           a[0][0], a[0][1], a[0][2], a[0][3], b0, b1);
            mma_16816_bf16(c[1][nt][0], c[1][nt][1], c[1][nt][2], c[1][nt][3],
                           a[1][0], a[1][1], a[1][2], a[1][3], b0, b1);
        }
    }
    __syncthreads();   // done reading As/Bs; A region becomes fp32 staging

    // ---- epilogue: act = exp(2*inv*dot - w2 - s2[p]) -> staged fp32 ----
    {
        float* stg = reinterpret_cast<float*>(dyn);
        #pragma unroll
        for (int m = 0; m < 2; m++) {
            #pragma unroll
            for (int half = 0; half < 2; half++) {
                const int rowL = wrp * 32 + m * 16 + g + half * 8;
                const int t    = t0 + rowL;
                const bool ok  = (t < TP_LEN);
                const float inv2 = 2.f * invs[rowL];
                const float cw   = w2s[rowL];
                #pragma unroll
                for (int nt = 0; nt < 8; nt++) {
                    const int col = nt * 8 + tq * 2;
                    float d0 = c[m][nt][half * 2 + 0];
                    float d1 = c[m][nt][half * 2 + 1];
                    float2 v;
                    v.x = ok ? __expf(fmaf(inv2, d0, -(cw + s2s[col])))     : 0.f;
                    v.y = ok ? __expf(fmaf(inv2, d1, -(cw + s2s[col + 1]))) : 0.f;
                    *reinterpret_cast<float2*>(stg + rowL * STG_W + col) = v;
                }
            }
        }
    }
    __syncthreads();

    // ---- coalesced store: 128 rows x 64 floats ----
    {
        float* outb = out + (size_t)b * T_LEN * P_NUM;
        const float* stg = reinterpret_cast<const float*>(dyn);
        #pragma unroll
        for (int it = 0; it < 16; it++) {
            int q    = tid + it * 128;
            int row  = q >> 4;
            int c4   = q & 15;
            int tout = t0 + row + PAD_LEFT;
            if (tout < T_LEN) {
                float4 v = *reinterpret_cast<const float4*>(stg + row * STG_W + c4 * 4);
                *reinterpret_cast<float4*>(outb + (size_t)tout * P_NUM + c4 * 4) = v;
            }
        }
        // left pad rows [0,32) -> zeros (tile 0 only)
        if (blockIdx.x == 0) {
            float4 z = make_float4(0.f, 0.f, 0.f, 0.f);
            #pragma unroll
            for (int it = 0; it < 4; it++) {
                int q   = tid + it * 128;
                int row = q >> 4;
                int c4  = q & 15;
                *reinterpret_cast<float4*>(outb + (size_t)row * P_NUM + c4 * 4) = z;
            }
        }
    }
}

extern "C" void kernel_launch(void* const* d_in, const int* in_sizes, int n_in,
                              void* d_out, int out_size) {
    const float* x  = (const float*)d_in[0];   // (32, 8192, 1)
    const float* sh = (const float*)d_in[1];   // (64, 1, 64)
    float* out = (float*)d_out;                // (32, 8192, 64)

    cudaFuncSetAttribute(shapelet_hmma_kernel,
                         cudaFuncAttributeMaxDynamicSharedMemorySize, DYN_SMEM);
    dim3 grid((TP_LEN + TILE_M - 1) / TILE_M, BS);   // (64, 32)
    shapelet_hmma_kernel<<<grid, 128, DYN_SMEM>>>(x, sh, out);
}